// round 14
// baseline (speedup 1.0000x reference)
#include <cuda_runtime.h>
#include <math.h>

#define B_TOTAL  16384
#define F_S      48
#define T_S      512
#define N_LAYERS 16
#define TILE_R   4
#define NTILES   (B_TOTAL / TILE_R)   // 4096
#define GRID     444                  // 3 CTAs x 148 SMs, all resident
#define THREADS  256
#define GPAD     72                   // float2 stride; conflict-free
#define GSIZE    (32 * GPAD)          // one Gs buffer (float2 count)

#define NBAR(id) asm volatile("bar.sync %0, 64;" :: "r"(id) : "memory")

// ---------------- device scratch ----------------
__device__ float2 g_R[B_TOTAL * T_S];          // 64 MB state (L2-resident)
__device__ float  g_partial[T_S * GRID];       // [t][cta]
__device__ float  g_gate[T_S];
__device__ float2 c_wd[8 * 64];                // e^{-2pi i d tp/512}
__device__ float2 c_cb[48];                    // e^{-2pi i c b/64} / sqrt(512)
__device__ float  g_scale[2];
__device__ float  g_maxpart[256];
__device__ unsigned g_bar_count;
__device__ volatile unsigned g_bar_gen;

// ---------------- complex helpers ----------------
__device__ __forceinline__ float2 cadd(float2 a, float2 b) { return make_float2(a.x + b.x, a.y + b.y); }
__device__ __forceinline__ float2 csub(float2 a, float2 b) { return make_float2(a.x - b.x, a.y - b.y); }
__device__ __forceinline__ float2 cmul(float2 a, float2 b) {
    return make_float2(fmaf(a.x, b.x, -a.y * b.y), fmaf(a.x, b.y, a.y * b.x));
}
__device__ __forceinline__ float2 cmulj(float2 a, float2 b) {   // a * conj(b)
    return make_float2(fmaf(a.x, b.x, a.y * b.y), fmaf(a.y, b.x, -a.x * b.y));
}

#define SQ2H 0.70710678118654752f

__device__ __forceinline__ void fft8f(const float2* h, float2* X) {
    float2 ea0 = cadd(h[0], h[4]), ea1 = csub(h[0], h[4]);
    float2 eb0 = cadd(h[2], h[6]), eb1 = csub(h[2], h[6]);
    float2 oa0 = cadd(h[1], h[5]), oa1 = csub(h[1], h[5]);
    float2 ob0 = cadd(h[3], h[7]), ob1 = csub(h[3], h[7]);
    float2 E0 = cadd(ea0, eb0), E2 = csub(ea0, eb0);
    float2 mieb = make_float2(eb1.y, -eb1.x);
    float2 E1 = cadd(ea1, mieb), E3 = csub(ea1, mieb);
    float2 O0 = cadd(oa0, ob0), O2 = csub(oa0, ob0);
    float2 miob = make_float2(ob1.y, -ob1.x);
    float2 O1 = cadd(oa1, miob), O3 = csub(oa1, miob);
    X[0] = cadd(E0, O0); X[4] = csub(E0, O0);
    float2 w1o = make_float2(SQ2H * (O1.x + O1.y), SQ2H * (O1.y - O1.x));
    X[1] = cadd(E1, w1o); X[5] = csub(E1, w1o);
    float2 w2o = make_float2(O2.y, -O2.x);
    X[2] = cadd(E2, w2o); X[6] = csub(E2, w2o);
    float2 w3o = make_float2(SQ2H * (O3.y - O3.x), -SQ2H * (O3.x + O3.y));
    X[3] = cadd(E3, w3o); X[7] = csub(E3, w3o);
}

__device__ __forceinline__ void fft8i(const float2* h, float2* X) {
    float2 ea0 = cadd(h[0], h[4]), ea1 = csub(h[0], h[4]);
    float2 eb0 = cadd(h[2], h[6]), eb1 = csub(h[2], h[6]);
    float2 oa0 = cadd(h[1], h[5]), oa1 = csub(h[1], h[5]);
    float2 ob0 = cadd(h[3], h[7]), ob1 = csub(h[3], h[7]);
    float2 E0 = cadd(ea0, eb0), E2 = csub(ea0, eb0);
    float2 pieb = make_float2(-eb1.y, eb1.x);
    float2 E1 = cadd(ea1, pieb), E3 = csub(ea1, pieb);
    float2 O0 = cadd(oa0, ob0), O2 = csub(oa0, ob0);
    float2 piob = make_float2(-ob1.y, ob1.x);
    float2 O1 = cadd(oa1, piob), O3 = csub(oa1, piob);
    X[0] = cadd(E0, O0); X[4] = csub(E0, O0);
    float2 w1o = make_float2(SQ2H * (O1.x - O1.y), SQ2H * (O1.x + O1.y));
    X[1] = cadd(E1, w1o); X[5] = csub(E1, w1o);
    float2 w2o = make_float2(-O2.y, O2.x);
    X[2] = cadd(E2, w2o); X[6] = csub(E2, w2o);
    float2 w3o = make_float2(-SQ2H * (O3.x + O3.y), SQ2H * (O3.x - O3.y));
    X[3] = cadd(E3, w3o); X[7] = csub(E3, w3o);
}

// ---------------- grid barrier ----------------
__device__ __forceinline__ void grid_bar() {
    __syncthreads();
    if (threadIdx.x == 0) {
        unsigned gen = g_bar_gen;
        __threadfence();
        if (atomicAdd(&g_bar_count, 1u) == GRID - 1u) {
            g_bar_count = 0;
            __threadfence();
            g_bar_gen = gen + 1u;
        } else {
            while (g_bar_gen == gen) __nanosleep(32);
        }
        __threadfence();
    }
    __syncthreads();
}

// ---------------- max reduction ----------------
__global__ void k_max1(const float* __restrict__ u, int n) {
    float m = -INFINITY;
    for (int i = blockIdx.x * blockDim.x + threadIdx.x; i < n; i += gridDim.x * blockDim.x)
        m = fmaxf(m, u[i]);
    __shared__ float sm[256];
    sm[threadIdx.x] = m;
    __syncthreads();
    for (int s = 128; s > 0; s >>= 1) {
        if (threadIdx.x < s) sm[threadIdx.x] = fmaxf(sm[threadIdx.x], sm[threadIdx.x + s]);
        __syncthreads();
    }
    if (threadIdx.x == 0) g_maxpart[blockIdx.x] = sm[0];
}

__global__ void k_max2() {
    __shared__ float sm[256];
    sm[threadIdx.x] = g_maxpart[threadIdx.x];
    __syncthreads();
    for (int s = 128; s > 0; s >>= 1) {
        if (threadIdx.x < s) sm[threadIdx.x] = fmaxf(sm[threadIdx.x], sm[threadIdx.x + s]);
        __syncthreads();
    }
    if (threadIdx.x == 0) {
        float m = fabsf(sm[0]);
        g_scale[0] = 5.0f / m;
        g_scale[1] = m / 5.0f;
    }
}

// ---------------- tables ----------------
__global__ void k_tw() {
    int i = blockIdx.x * blockDim.x + threadIdx.x;
    if (i < 8 * 64) {
        int d = i >> 6, tp = i & 63;
        double ang = 2.0 * M_PI * (double)(d * tp) / 512.0;
        double s, c; sincos(ang, &s, &c);
        c_wd[i] = make_float2((float)c, (float)(-s));
    }
    if (i < 48) {
        int cc = i >> 3, b = i & 7;
        double sc = 1.0 / sqrt(512.0);
        double ang = 2.0 * M_PI * (double)(cc * b) / 64.0;
        double s, c; sincos(ang, &s, &c);
        c_cb[i] = make_float2((float)(c * sc), (float)(-s * sc));
    }
}

// ---------------- persistent fused network kernel ----------------
extern __shared__ float smem_raw[];

__global__ void __launch_bounds__(THREADS, 3)
k_net(const float* __restrict__ u, const float* __restrict__ S1,
      const float* __restrict__ S2, float* __restrict__ out) {
    float2* Gs   = (float2*)smem_raw;                  // [2][32][GPAD] 36.9 KB
    float2* wds  = Gs + 2 * GSIZE;                     // [512]          4 KB
    float2* cbs  = wds + 8 * 64;                       // [48]           0.4 KB
    float*  ps2  = (float*)(cbs + 48);                 // [4][512]       8 KB
    float*  redg = ps2 + 4 * T_S;                      // [8] cross-warp gate slots

    const int tid = threadIdx.x;
    const float s_in = g_scale[0];
    const int r  = tid >> 6;          // group within CTA
    const int tp = tid & 63;          // G/Z-stage time-within-64
    const int b  = tid & 7;           // A/S-stage radix lane
    const int d  = (tid >> 3) & 7;    // A/S-stage digit
    const int bar_id = r + 1;
    const int gid = blockIdx.x * TILE_R + r;   // global group id (gate stage)

    // stage twiddle tables into smem
    for (int i = tid; i < 8 * 64; i += THREADS) wds[i] = c_wd[i];
    if (tid < 48) cbs[tid] = c_cb[tid];
    __syncthreads();

    float2 cbv[6];
#pragma unroll
    for (int c = 0; c < 6; ++c) cbv[c] = cbs[c * 8 + b];

    for (int layer = 0; layer <= N_LAYERS; ++layer) {
        const bool first = (layer == 0);
        const bool last  = (layer == N_LAYERS);

        // gate values this thread needs, in registers (t = 64q + tp)
        float gvv[8];
        if (!first) {
#pragma unroll
            for (int q = 0; q < 8; ++q) gvv[q] = __ldcg(&g_gate[(q << 6) + tp]);
        }

        float acc[8];                              // per-thread |R|^2 partials
#pragma unroll
        for (int q = 0; q < 8; ++q) acc[q] = 0.f;

        int par = 0;
        for (int tile = blockIdx.x; tile < NTILES; tile += GRID) {
            const int b0 = tile * TILE_R;
            float2* Gb = Gs + par * GSIZE;

            // ---- stage G: hh = R*g (regs); Gb[r][dd][tp] = wd[dd][tp] * fft8_q(hh) ----
            float2 hh[8];
            if (!first) {
                float2 X[8];
#pragma unroll
                for (int q = 0; q < 8; ++q) {
                    float2 Rv = __ldcg(&g_R[(b0 + r) * T_S + (q << 6) + tp]);
                    hh[q] = make_float2(Rv.x * gvv[q], Rv.y * gvv[q]);
                }
                fft8f(hh, X);
#pragma unroll
                for (int dd = 0; dd < 8; ++dd)
                    Gb[(r * 8 + dd) * GPAD + tp] = cmul(X[dd], wds[(dd << 6) + tp]);
            } else {
#pragma unroll
                for (int q = 0; q < 8; ++q) hh[q] = make_float2(0.f, 0.f);
            }
            NBAR(bar_id);

            // ---- fused stage A+S (role (r,d,b)) ----
            {
                // hoisted u loads: overlap L2 latency with the fft/shfl chain below
                float2 uvv[6];
#pragma unroll
                for (int c = 0; c < 6; ++c)
                    uvv[c] = ((const float2*)u)[(b0 + r) * F_S + (c << 3) + d];

                float2 p[6];
                if (!first) {
                    float2 Gv[8], A[8];
#pragma unroll
                    for (int a = 0; a < 8; ++a) Gv[a] = Gb[(r * 8 + d) * GPAD + (a << 3) + b];
                    fft8f(Gv, A);
#pragma unroll
                    for (int c = 0; c < 6; ++c) p[c] = cmul(A[c], cbv[c]);
#pragma unroll
                    for (int m = 1; m < 8; m <<= 1) {
#pragma unroll
                        for (int c = 0; c < 6; ++c) {
                            p[c].x += __shfl_xor_sync(0xFFFFFFFFu, p[c].x, m);
                            p[c].y += __shfl_xor_sync(0xFFFFFFFFu, p[c].y, m);
                        }
                    }
                } else {
#pragma unroll
                    for (int c = 0; c < 6; ++c) p[c] = make_float2(0.f, 0.f);
                }

                if (last) {
                    if (b == 0) {
                        const float s_out = g_scale[1];
#pragma unroll
                        for (int c = 0; c < 6; ++c)
                            ((float2*)out)[(b0 + r) * F_S + (c << 3) + d] =
                                make_float2(p[c].x * s_out, p[c].y * s_out);
                    }
                    par ^= 1;      // double buffer: next G writes other half
                    continue;
                }

                float2 v[8], S[8];
#pragma unroll
                for (int c = 0; c < 6; ++c) {
                    float2 z = make_float2(uvv[c].x * s_in - p[c].x, uvv[c].y * s_in - p[c].y);
                    v[c] = cmulj(z, cbv[c]);
                }
                v[6] = make_float2(0.f, 0.f);
                v[7] = make_float2(0.f, 0.f);
                fft8i(v, S);
#pragma unroll
                for (int a = 0; a < 8; ++a)
                    Gb[(r * 8 + d) * GPAD + (a << 3) + b] = S[a];   // same slots this thread read
            }
            NBAR(bar_id);

            // ---- stage Z/R: Z = ifft8_d( Gb[d][tp] * conj(wd[d][tp]) ); R = hh + Z ----
            {
                float2 v[8], Z[8];
#pragma unroll
                for (int dd = 0; dd < 8; ++dd)
                    v[dd] = cmulj(Gb[(r * 8 + dd) * GPAD + tp], wds[(dd << 6) + tp]);
                fft8i(v, Z);
#pragma unroll
                for (int q = 0; q < 8; ++q) {
                    float Rr = Z[q].x + hh[q].x;
                    float Ri = Z[q].y + hh[q].y;
                    g_R[(b0 + r) * T_S + (q << 6) + tp] = make_float2(Rr, Ri);
                    acc[q] = fmaf(Rr, Rr, fmaf(Ri, Ri, acc[q]));
                }
            }
            par ^= 1;              // double buffer: next G writes other half, no barrier
        }
        if (last) break;

        // ---- per-layer |R|^2 reduction: regs -> smem (r groups) -> per-CTA partial ----
#pragma unroll
        for (int q = 0; q < 8; ++q) ps2[r * T_S + (q << 6) + tp] = acc[q];
        __syncthreads();
        for (int t = tid; t < T_S; t += THREADS)
            g_partial[t * GRID + blockIdx.x] =
                ps2[t] + ps2[T_S + t] + ps2[2 * T_S + t] + ps2[3 * T_S + t];
        grid_bar();

        // -------- gate stage: group gid handles t = gid (one t per group) --------
        if (gid < T_S) {
            const int t = gid;
            float s = 0.f;
            for (int j = tp; j < GRID; j += 64)
                s += __ldcg(&g_partial[t * GRID + j]);
#pragma unroll
            for (int m = 16; m > 0; m >>= 1)
                s += __shfl_xor_sync(0xFFFFFFFFu, s, m);
            if ((tid & 31) == 0) redg[(tid >> 5)] = s;   // slots 2r, 2r+1
            NBAR(bar_id);
            if (tp == 0) {
                float tot = redg[2 * r] + redg[2 * r + 1];
                float rmean = sqrtf(tot * (1.0f / (float)B_TOTAL));
                float x = S1[0] * (rmean - S2[0]);
                g_gate[t] = 1.0f / (1.0f + expf(-x));
            }
        }
        grid_bar();
    }
}

// ---------------- launch ----------------
extern "C" void kernel_launch(void* const* d_in, const int* in_sizes, int n_in,
                              void* d_out, int out_size) {
    const float* u  = (const float*)d_in[0];
    const float* S1 = (const float*)d_in[1];
    const float* S2 = (const float*)d_in[2];
    float* out = (float*)d_out;

    const int smem = (2 * GSIZE + 8 * 64 + 48) * (int)sizeof(float2)
                   + (4 * T_S + 8) * (int)sizeof(float);
    cudaFuncSetAttribute(k_net, cudaFuncAttributeMaxDynamicSharedMemorySize, smem);

    const int n = B_TOTAL * F_S * 2;
    k_max1<<<256, 256>>>(u, n);
    k_max2<<<1, 256>>>();
    k_tw<<<2, 256>>>();
    k_net<<<GRID, THREADS, smem>>>(u, S1, S2, out);

    (void)in_sizes; (void)n_in; (void)out_size;
}

// round 15
// speedup vs baseline: 1.0790x; 1.0790x over previous
#include <cuda_runtime.h>
#include <math.h>

#define B_TOTAL  16384
#define F_S      48
#define T_S      512
#define N_LAYERS 16
#define TILE_R   4
#define NTILES   (B_TOTAL / TILE_R)   // 4096
#define GRID     444                  // 3 CTAs x 148 SMs, all resident
#define THREADS  256
#define GPAD     72                   // float2 stride; conflict-free
#define GSIZE    (32 * GPAD)          // one Gs buffer (float2 count)

#define NBAR(id) asm volatile("bar.sync %0, 64;" :: "r"(id) : "memory")

// ---------------- packed complex (f32x2) ----------------
typedef unsigned long long cplx;     // lanes: (re, im)

__device__ __forceinline__ cplx PK(float x, float y) {
    cplx r; asm("mov.b64 %0, {%1, %2};" : "=l"(r) : "f"(x), "f"(y)); return r;
}
__device__ __forceinline__ float2 UPK(cplx a) {
    float2 v; asm("mov.b64 {%0, %1}, %2;" : "=f"(v.x), "=f"(v.y) : "l"(a)); return v;
}
__device__ __forceinline__ cplx f2add(cplx a, cplx b) {
    cplx r; asm("add.rn.f32x2 %0, %1, %2;" : "=l"(r) : "l"(a), "l"(b)); return r;
}
__device__ __forceinline__ cplx f2sub(cplx a, cplx b) {
    cplx r; asm("sub.rn.f32x2 %0, %1, %2;" : "=l"(r) : "l"(a), "l"(b)); return r;
}
__device__ __forceinline__ cplx f2mul(cplx a, cplx b) {
    cplx r; asm("mul.rn.f32x2 %0, %1, %2;" : "=l"(r) : "l"(a), "l"(b)); return r;
}
__device__ __forceinline__ cplx cmi(cplx a) {    // -i * a
    float2 v = UPK(a); return PK(v.y, -v.x);
}
__device__ __forceinline__ cplx cpi(cplx a) {    // +i * a
    float2 v = UPK(a); return PK(-v.y, v.x);
}

// scalar complex helpers (for twiddle multiplies)
__device__ __forceinline__ float2 cmul(float2 a, float2 b) {
    return make_float2(fmaf(a.x, b.x, -a.y * b.y), fmaf(a.x, b.y, a.y * b.x));
}
__device__ __forceinline__ float2 cmulj(float2 a, float2 b) {   // a * conj(b)
    return make_float2(fmaf(a.x, b.x, a.y * b.y), fmaf(a.y, b.x, -a.x * b.y));
}

#define SQ2H 0.70710678118654752f

// X[k] = sum_n h[n] e^{-2pi i nk/8}   (packed)
__device__ __forceinline__ void fft8f(const cplx* h, cplx* X) {
    cplx ea0 = f2add(h[0], h[4]), ea1 = f2sub(h[0], h[4]);
    cplx eb0 = f2add(h[2], h[6]), eb1 = f2sub(h[2], h[6]);
    cplx oa0 = f2add(h[1], h[5]), oa1 = f2sub(h[1], h[5]);
    cplx ob0 = f2add(h[3], h[7]), ob1 = f2sub(h[3], h[7]);
    cplx E0 = f2add(ea0, eb0), E2 = f2sub(ea0, eb0);
    cplx mieb = cmi(eb1);
    cplx E1 = f2add(ea1, mieb), E3 = f2sub(ea1, mieb);
    cplx O0 = f2add(oa0, ob0), O2 = f2sub(oa0, ob0);
    cplx miob = cmi(ob1);
    cplx O1 = f2add(oa1, miob), O3 = f2sub(oa1, miob);
    X[0] = f2add(E0, O0); X[4] = f2sub(E0, O0);
    float2 o1 = UPK(O1);
    cplx w1o = PK(SQ2H * (o1.x + o1.y), SQ2H * (o1.y - o1.x));   // s(1-i)*O1
    X[1] = f2add(E1, w1o); X[5] = f2sub(E1, w1o);
    cplx w2o = cmi(O2);
    X[2] = f2add(E2, w2o); X[6] = f2sub(E2, w2o);
    float2 o3 = UPK(O3);
    cplx w3o = PK(SQ2H * (o3.y - o3.x), -SQ2H * (o3.x + o3.y));  // -s(1+i)*O3
    X[3] = f2add(E3, w3o); X[7] = f2sub(E3, w3o);
}

// X[k] = sum_n h[n] e^{+2pi i nk/8}   (packed)
__device__ __forceinline__ void fft8i(const cplx* h, cplx* X) {
    cplx ea0 = f2add(h[0], h[4]), ea1 = f2sub(h[0], h[4]);
    cplx eb0 = f2add(h[2], h[6]), eb1 = f2sub(h[2], h[6]);
    cplx oa0 = f2add(h[1], h[5]), oa1 = f2sub(h[1], h[5]);
    cplx ob0 = f2add(h[3], h[7]), ob1 = f2sub(h[3], h[7]);
    cplx E0 = f2add(ea0, eb0), E2 = f2sub(ea0, eb0);
    cplx pieb = cpi(eb1);
    cplx E1 = f2add(ea1, pieb), E3 = f2sub(ea1, pieb);
    cplx O0 = f2add(oa0, ob0), O2 = f2sub(oa0, ob0);
    cplx piob = cpi(ob1);
    cplx O1 = f2add(oa1, piob), O3 = f2sub(oa1, piob);
    X[0] = f2add(E0, O0); X[4] = f2sub(E0, O0);
    float2 o1 = UPK(O1);
    cplx w1o = PK(SQ2H * (o1.x - o1.y), SQ2H * (o1.x + o1.y));   // s(1+i)*O1
    X[1] = f2add(E1, w1o); X[5] = f2sub(E1, w1o);
    cplx w2o = cpi(O2);
    X[2] = f2add(E2, w2o); X[6] = f2sub(E2, w2o);
    float2 o3 = UPK(O3);
    cplx w3o = PK(-SQ2H * (o3.x + o3.y), SQ2H * (o3.x - o3.y));  // s(-1+i)*O3
    X[3] = f2add(E3, w3o); X[7] = f2sub(E3, w3o);
}

// ---------------- device scratch ----------------
__device__ cplx  g_R[B_TOTAL * T_S];           // 64 MB state (L2-resident)
__device__ float g_partial[T_S * GRID];        // [t][cta]
__device__ float g_gate[T_S];
__device__ float2 c_wd[8 * 64];                // e^{-2pi i d tp/512}
__device__ float2 c_cb[48];                    // e^{-2pi i c b/64} / sqrt(512)
__device__ float g_scale[2];
__device__ float g_maxpart[256];
__device__ unsigned g_bar_count;
__device__ volatile unsigned g_bar_gen;

// ---------------- grid barrier ----------------
__device__ __forceinline__ void grid_bar() {
    __syncthreads();
    if (threadIdx.x == 0) {
        unsigned gen = g_bar_gen;
        __threadfence();
        if (atomicAdd(&g_bar_count, 1u) == GRID - 1u) {
            g_bar_count = 0;
            __threadfence();
            g_bar_gen = gen + 1u;
        } else {
            while (g_bar_gen == gen) __nanosleep(64);
        }
        __threadfence();
    }
    __syncthreads();
}

// ---------------- max reduction ----------------
__global__ void k_max1(const float* __restrict__ u, int n) {
    float m = -INFINITY;
    for (int i = blockIdx.x * blockDim.x + threadIdx.x; i < n; i += gridDim.x * blockDim.x)
        m = fmaxf(m, u[i]);
    __shared__ float sm[256];
    sm[threadIdx.x] = m;
    __syncthreads();
    for (int s = 128; s > 0; s >>= 1) {
        if (threadIdx.x < s) sm[threadIdx.x] = fmaxf(sm[threadIdx.x], sm[threadIdx.x + s]);
        __syncthreads();
    }
    if (threadIdx.x == 0) g_maxpart[blockIdx.x] = sm[0];
}

__global__ void k_max2() {
    __shared__ float sm[256];
    sm[threadIdx.x] = g_maxpart[threadIdx.x];
    __syncthreads();
    for (int s = 128; s > 0; s >>= 1) {
        if (threadIdx.x < s) sm[threadIdx.x] = fmaxf(sm[threadIdx.x], sm[threadIdx.x + s]);
        __syncthreads();
    }
    if (threadIdx.x == 0) {
        float m = fabsf(sm[0]);
        g_scale[0] = 5.0f / m;
        g_scale[1] = m / 5.0f;
    }
}

// ---------------- tables ----------------
__global__ void k_tw() {
    int i = blockIdx.x * blockDim.x + threadIdx.x;
    if (i < 8 * 64) {
        int d = i >> 6, tp = i & 63;
        double ang = 2.0 * M_PI * (double)(d * tp) / 512.0;
        double s, c; sincos(ang, &s, &c);
        c_wd[i] = make_float2((float)c, (float)(-s));
    }
    if (i < 48) {
        int cc = i >> 3, b = i & 7;
        double sc = 1.0 / sqrt(512.0);
        double ang = 2.0 * M_PI * (double)(cc * b) / 64.0;
        double s, c; sincos(ang, &s, &c);
        c_cb[i] = make_float2((float)(c * sc), (float)(-s * sc));
    }
}

// ---------------- persistent fused network kernel ----------------
extern __shared__ float smem_raw[];

__global__ void __launch_bounds__(THREADS, 3)
k_net(const float* __restrict__ u, const float* __restrict__ S1,
      const float* __restrict__ S2, float* __restrict__ out) {
    cplx*   Gs   = (cplx*)smem_raw;                    // [2][32][GPAD] 36.9 KB
    float2* wds  = (float2*)(Gs + 2 * GSIZE);          // [512]          4 KB
    float2* cbs  = wds + 8 * 64;                       // [48]           0.4 KB
    float*  ps2  = (float*)(cbs + 48);                 // [4][512]       8 KB
    float*  red  = ps2 + 4 * T_S;                      // [256]          1 KB

    const int tid = threadIdx.x;
    const float s_in = g_scale[0];
    const int r  = tid >> 6;          // group within CTA
    const int tp = tid & 63;          // G/Z-stage time-within-64
    const int b  = tid & 7;           // A/S-stage radix lane
    const int d  = (tid >> 3) & 7;    // A/S-stage digit
    const int bar_id = r + 1;

    // stage twiddle tables into smem
    for (int i = tid; i < 8 * 64; i += THREADS) wds[i] = c_wd[i];
    if (tid < 48) cbs[tid] = c_cb[tid];
    __syncthreads();

    float2 cbv[6];
#pragma unroll
    for (int c = 0; c < 6; ++c) cbv[c] = cbs[c * 8 + b];

    for (int layer = 0; layer <= N_LAYERS; ++layer) {
        const bool first = (layer == 0);
        const bool last  = (layer == N_LAYERS);

        // gate values this thread needs, in registers (t = 64q + tp)
        float gvv[8];
        if (!first) {
#pragma unroll
            for (int q = 0; q < 8; ++q) gvv[q] = __ldcg(&g_gate[(q << 6) + tp]);
        }

        float acc[8];                              // per-thread |R|^2 partials
#pragma unroll
        for (int q = 0; q < 8; ++q) acc[q] = 0.f;

        int par = 0;
        for (int tile = blockIdx.x; tile < NTILES; tile += GRID) {
            const int b0 = tile * TILE_R;
            cplx* Gb = Gs + par * GSIZE;

            // ---- stage G: hh = R*g (regs); Gb[r][dd][tp] = wd[dd][tp] * fft8_q(hh) ----
            cplx hh[8];
            if (!first) {
                cplx X[8];
#pragma unroll
                for (int q = 0; q < 8; ++q) {
                    cplx Rv = __ldcg(&g_R[(b0 + r) * T_S + (q << 6) + tp]);
                    hh[q] = f2mul(Rv, PK(gvv[q], gvv[q]));
                }
                fft8f(hh, X);
#pragma unroll
                for (int dd = 0; dd < 8; ++dd) {
                    float2 x = UPK(X[dd]);
                    float2 y = cmul(x, wds[(dd << 6) + tp]);
                    Gb[(r * 8 + dd) * GPAD + tp] = PK(y.x, y.y);
                }
            } else {
#pragma unroll
                for (int q = 0; q < 8; ++q) hh[q] = PK(0.f, 0.f);
            }
            NBAR(bar_id);

            // ---- fused stage A+S (role (r,d,b)) ----
            {
                float2 p[6];
                if (!first) {
                    cplx Gv[8], A[8];
#pragma unroll
                    for (int a = 0; a < 8; ++a) Gv[a] = Gb[(r * 8 + d) * GPAD + (a << 3) + b];
                    fft8f(Gv, A);
#pragma unroll
                    for (int c = 0; c < 6; ++c) p[c] = cmul(UPK(A[c]), cbv[c]);
#pragma unroll
                    for (int m = 1; m < 8; m <<= 1) {
#pragma unroll
                        for (int c = 0; c < 6; ++c) {
                            p[c].x += __shfl_xor_sync(0xFFFFFFFFu, p[c].x, m);
                            p[c].y += __shfl_xor_sync(0xFFFFFFFFu, p[c].y, m);
                        }
                    }
                } else {
#pragma unroll
                    for (int c = 0; c < 6; ++c) p[c] = make_float2(0.f, 0.f);
                }

                if (last) {
                    if (b == 0) {
                        const float s_out = g_scale[1];
#pragma unroll
                        for (int c = 0; c < 6; ++c)
                            ((float2*)out)[(b0 + r) * F_S + (c << 3) + d] =
                                make_float2(p[c].x * s_out, p[c].y * s_out);
                    }
                    par ^= 1;      // double buffer: next G writes other half
                    continue;
                }

                cplx v[8], S[8];
#pragma unroll
                for (int c = 0; c < 6; ++c) {
                    float2 uv = ((const float2*)u)[(b0 + r) * F_S + (c << 3) + d];
                    float2 z = make_float2(uv.x * s_in - p[c].x, uv.y * s_in - p[c].y);
                    float2 w = cmulj(z, cbv[c]);
                    v[c] = PK(w.x, w.y);
                }
                v[6] = PK(0.f, 0.f);
                v[7] = PK(0.f, 0.f);
                fft8i(v, S);
#pragma unroll
                for (int a = 0; a < 8; ++a)
                    Gb[(r * 8 + d) * GPAD + (a << 3) + b] = S[a];   // same slots this thread read
            }
            NBAR(bar_id);

            // ---- stage Z/R: Z = ifft8_d( Gb[d][tp] * conj(wd[d][tp]) ); R = hh + Z ----
            {
                cplx v[8], Z[8];
#pragma unroll
                for (int dd = 0; dd < 8; ++dd) {
                    float2 g = UPK(Gb[(r * 8 + dd) * GPAD + tp]);
                    float2 w = cmulj(g, wds[(dd << 6) + tp]);
                    v[dd] = PK(w.x, w.y);
                }
                fft8i(v, Z);
#pragma unroll
                for (int q = 0; q < 8; ++q) {
                    cplx Rp = f2add(Z[q], hh[q]);
                    g_R[(b0 + r) * T_S + (q << 6) + tp] = Rp;
                    float2 Rv = UPK(Rp);
                    acc[q] = fmaf(Rv.x, Rv.x, fmaf(Rv.y, Rv.y, acc[q]));
                }
            }
            par ^= 1;              // double buffer: next G writes other half, no barrier
        }
        if (last) break;

        // ---- per-layer |R|^2 reduction: regs -> smem (r groups) -> per-CTA partial ----
#pragma unroll
        for (int q = 0; q < 8; ++q) ps2[r * T_S + (q << 6) + tp] = acc[q];
        __syncthreads();
        for (int t = tid; t < T_S; t += THREADS)
            g_partial[t * GRID + blockIdx.x] =
                ps2[t] + ps2[T_S + t] + ps2[2 * T_S + t] + ps2[3 * T_S + t];
        grid_bar();

        // -------- gate stage --------
        for (int t = blockIdx.x; t < T_S; t += GRID) {
            float s = __ldcg(&g_partial[t * GRID + tid]);
            if (tid + 256 < GRID) s += __ldcg(&g_partial[t * GRID + tid + 256]);
            red[tid] = s;
            __syncthreads();
            for (int k = 128; k > 0; k >>= 1) {
                if (tid < k) red[tid] += red[tid + k];
                __syncthreads();
            }
            if (tid == 0) {
                float rmean = sqrtf(red[0] * (1.0f / (float)B_TOTAL));
                float x = S1[0] * (rmean - S2[0]);
                g_gate[t] = 1.0f / (1.0f + expf(-x));
            }
            __syncthreads();
        }
        grid_bar();
    }
}

// ---------------- launch ----------------
extern "C" void kernel_launch(void* const* d_in, const int* in_sizes, int n_in,
                              void* d_out, int out_size) {
    const float* u  = (const float*)d_in[0];
    const float* S1 = (const float*)d_in[1];
    const float* S2 = (const float*)d_in[2];
    float* out = (float*)d_out;

    const int smem = (2 * GSIZE) * (int)sizeof(cplx)
                   + (8 * 64 + 48) * (int)sizeof(float2)
                   + (4 * T_S + THREADS) * (int)sizeof(float);
    cudaFuncSetAttribute(k_net, cudaFuncAttributeMaxDynamicSharedMemorySize, smem);

    const int n = B_TOTAL * F_S * 2;
    k_max1<<<256, 256>>>(u, n);
    k_max2<<<1, 256>>>();
    k_tw<<<2, 256>>>();
    k_net<<<GRID, THREADS, smem>>>(u, S1, S2, out);

    (void)in_sizes; (void)n_in; (void)out_size;
}

// round 16
// speedup vs baseline: 1.1088x; 1.0277x over previous
#include <cuda_runtime.h>
#include <math.h>

#define B_TOTAL  16384
#define F_S      48
#define T_S      512
#define N_LAYERS 16
#define TILE_R   4
#define NTILES   (B_TOTAL / TILE_R)   // 4096
#define GRID     444                  // 3 CTAs x 148 SMs, all resident
#define THREADS  256
#define GPAD     72                   // cplx stride; conflict-free
#define GSIZE    (32 * GPAD)          // one Gs buffer (cplx count)

#define NBAR(id) asm volatile("bar.sync %0, 64;" :: "r"(id) : "memory")

// ---------------- packed complex (f32x2) ----------------
typedef unsigned long long cplx;     // lanes: (re, im)

__device__ __forceinline__ cplx PK(float x, float y) {
    cplx r; asm("mov.b64 %0, {%1, %2};" : "=l"(r) : "f"(x), "f"(y)); return r;
}
__device__ __forceinline__ float2 UPK(cplx a) {
    float2 v; asm("mov.b64 {%0, %1}, %2;" : "=f"(v.x), "=f"(v.y) : "l"(a)); return v;
}
__device__ __forceinline__ cplx f2add(cplx a, cplx b) {
    cplx r; asm("add.rn.f32x2 %0, %1, %2;" : "=l"(r) : "l"(a), "l"(b)); return r;
}
__device__ __forceinline__ cplx f2sub(cplx a, cplx b) {
    cplx r; asm("sub.rn.f32x2 %0, %1, %2;" : "=l"(r) : "l"(a), "l"(b)); return r;
}
__device__ __forceinline__ cplx f2mul(cplx a, cplx b) {
    cplx r; asm("mul.rn.f32x2 %0, %1, %2;" : "=l"(r) : "l"(a), "l"(b)); return r;
}
__device__ __forceinline__ cplx cmi(cplx a) {    // -i * a
    float2 v = UPK(a); return PK(v.y, -v.x);
}
__device__ __forceinline__ cplx cpi(cplx a) {    // +i * a
    float2 v = UPK(a); return PK(-v.y, v.x);
}

// scalar complex helpers (for twiddle multiplies)
__device__ __forceinline__ float2 cmul(float2 a, float2 b) {
    return make_float2(fmaf(a.x, b.x, -a.y * b.y), fmaf(a.x, b.y, a.y * b.x));
}
__device__ __forceinline__ float2 cmulj(float2 a, float2 b) {   // a * conj(b)
    return make_float2(fmaf(a.x, b.x, a.y * b.y), fmaf(a.y, b.x, -a.x * b.y));
}

#define SQ2H 0.70710678118654752f

// X[k] = sum_n h[n] e^{-2pi i nk/8}   (packed)
__device__ __forceinline__ void fft8f(const cplx* h, cplx* X) {
    cplx ea0 = f2add(h[0], h[4]), ea1 = f2sub(h[0], h[4]);
    cplx eb0 = f2add(h[2], h[6]), eb1 = f2sub(h[2], h[6]);
    cplx oa0 = f2add(h[1], h[5]), oa1 = f2sub(h[1], h[5]);
    cplx ob0 = f2add(h[3], h[7]), ob1 = f2sub(h[3], h[7]);
    cplx E0 = f2add(ea0, eb0), E2 = f2sub(ea0, eb0);
    cplx mieb = cmi(eb1);
    cplx E1 = f2add(ea1, mieb), E3 = f2sub(ea1, mieb);
    cplx O0 = f2add(oa0, ob0), O2 = f2sub(oa0, ob0);
    cplx miob = cmi(ob1);
    cplx O1 = f2add(oa1, miob), O3 = f2sub(oa1, miob);
    X[0] = f2add(E0, O0); X[4] = f2sub(E0, O0);
    float2 o1 = UPK(O1);
    cplx w1o = PK(SQ2H * (o1.x + o1.y), SQ2H * (o1.y - o1.x));   // s(1-i)*O1
    X[1] = f2add(E1, w1o); X[5] = f2sub(E1, w1o);
    cplx w2o = cmi(O2);
    X[2] = f2add(E2, w2o); X[6] = f2sub(E2, w2o);
    float2 o3 = UPK(O3);
    cplx w3o = PK(SQ2H * (o3.y - o3.x), -SQ2H * (o3.x + o3.y));  // -s(1+i)*O3
    X[3] = f2add(E3, w3o); X[7] = f2sub(E3, w3o);
}

// X[k] = sum_n h[n] e^{+2pi i nk/8}   (packed)
__device__ __forceinline__ void fft8i(const cplx* h, cplx* X) {
    cplx ea0 = f2add(h[0], h[4]), ea1 = f2sub(h[0], h[4]);
    cplx eb0 = f2add(h[2], h[6]), eb1 = f2sub(h[2], h[6]);
    cplx oa0 = f2add(h[1], h[5]), oa1 = f2sub(h[1], h[5]);
    cplx ob0 = f2add(h[3], h[7]), ob1 = f2sub(h[3], h[7]);
    cplx E0 = f2add(ea0, eb0), E2 = f2sub(ea0, eb0);
    cplx pieb = cpi(eb1);
    cplx E1 = f2add(ea1, pieb), E3 = f2sub(ea1, pieb);
    cplx O0 = f2add(oa0, ob0), O2 = f2sub(oa0, ob0);
    cplx piob = cpi(ob1);
    cplx O1 = f2add(oa1, piob), O3 = f2sub(oa1, piob);
    X[0] = f2add(E0, O0); X[4] = f2sub(E0, O0);
    float2 o1 = UPK(O1);
    cplx w1o = PK(SQ2H * (o1.x - o1.y), SQ2H * (o1.x + o1.y));   // s(1+i)*O1
    X[1] = f2add(E1, w1o); X[5] = f2sub(E1, w1o);
    cplx w2o = cpi(O2);
    X[2] = f2add(E2, w2o); X[6] = f2sub(E2, w2o);
    float2 o3 = UPK(O3);
    cplx w3o = PK(-SQ2H * (o3.x + o3.y), SQ2H * (o3.x - o3.y));  // s(-1+i)*O3
    X[3] = f2add(E3, w3o); X[7] = f2sub(E3, w3o);
}

// ---------------- device scratch ----------------
__device__ cplx  g_R[B_TOTAL * T_S];           // 64 MB state (L2-resident)
__device__ float g_partial[T_S * GRID];        // [t][cta]
__device__ float g_gate[T_S];
__device__ float2 c_wd[8 * 64];                // e^{-2pi i d tp/512}
__device__ float2 c_cb[48];                    // e^{-2pi i c b/64} / sqrt(512)
__device__ float g_scale[2];
__device__ float g_maxpart[256];
__device__ unsigned g_bar_count;
__device__ volatile unsigned g_bar_gen;

// ---------------- grid barrier ----------------
__device__ __forceinline__ void grid_bar() {
    __syncthreads();
    if (threadIdx.x == 0) {
        unsigned gen = g_bar_gen;
        __threadfence();
        if (atomicAdd(&g_bar_count, 1u) == GRID - 1u) {
            g_bar_count = 0;
            __threadfence();
            g_bar_gen = gen + 1u;
        } else {
            while (g_bar_gen == gen) __nanosleep(64);
        }
        __threadfence();
    }
    __syncthreads();
}

// ---------------- max reduction ----------------
__global__ void k_max1(const float* __restrict__ u, int n) {
    float m = -INFINITY;
    for (int i = blockIdx.x * blockDim.x + threadIdx.x; i < n; i += gridDim.x * blockDim.x)
        m = fmaxf(m, u[i]);
    __shared__ float sm[256];
    sm[threadIdx.x] = m;
    __syncthreads();
    for (int s = 128; s > 0; s >>= 1) {
        if (threadIdx.x < s) sm[threadIdx.x] = fmaxf(sm[threadIdx.x], sm[threadIdx.x + s]);
        __syncthreads();
    }
    if (threadIdx.x == 0) g_maxpart[blockIdx.x] = sm[0];
}

__global__ void k_max2() {
    __shared__ float sm[256];
    sm[threadIdx.x] = g_maxpart[threadIdx.x];
    __syncthreads();
    for (int s = 128; s > 0; s >>= 1) {
        if (threadIdx.x < s) sm[threadIdx.x] = fmaxf(sm[threadIdx.x], sm[threadIdx.x + s]);
        __syncthreads();
    }
    if (threadIdx.x == 0) {
        float m = fabsf(sm[0]);
        g_scale[0] = 5.0f / m;
        g_scale[1] = m / 5.0f;
    }
}

// ---------------- tables ----------------
__global__ void k_tw() {
    int i = blockIdx.x * blockDim.x + threadIdx.x;
    if (i < 8 * 64) {
        int d = i >> 6, tp = i & 63;
        double ang = 2.0 * M_PI * (double)(d * tp) / 512.0;
        double s, c; sincos(ang, &s, &c);
        c_wd[i] = make_float2((float)c, (float)(-s));
    }
    if (i < 48) {
        int cc = i >> 3, b = i & 7;
        double sc = 1.0 / sqrt(512.0);
        double ang = 2.0 * M_PI * (double)(cc * b) / 64.0;
        double s, c; sincos(ang, &s, &c);
        c_cb[i] = make_float2((float)(c * sc), (float)(-s * sc));
    }
}

// ---------------- persistent fused network kernel ----------------
extern __shared__ float smem_raw[];

__global__ void __launch_bounds__(THREADS, 3)
k_net(const float* __restrict__ u, const float* __restrict__ S1,
      const float* __restrict__ S2, float* __restrict__ out) {
    cplx*   Gs   = (cplx*)smem_raw;                    // [2][32][GPAD] 36.9 KB
    float2* cbs  = (float2*)(Gs + 2 * GSIZE);          // [48]           0.4 KB
    float*  ps2  = (float*)(cbs + 48);                 // [4][512]       8 KB
    float*  red  = ps2 + 4 * T_S;                      // [256]          1 KB

    const int tid = threadIdx.x;
    const float s_in = g_scale[0];
    const int r  = tid >> 6;          // group within CTA
    const int tp = tid & 63;          // G/Z-stage time-within-64
    const int b  = tid & 7;           // A/S-stage radix lane
    const int d  = (tid >> 3) & 7;    // A/S-stage digit
    const int bar_id = r + 1;

    // per-thread twiddles: tile- and layer-invariant -> registers
    cplx wtw[8];
#pragma unroll
    for (int dd = 0; dd < 8; ++dd) {
        float2 w = c_wd[(dd << 6) + tp];
        wtw[dd] = PK(w.x, w.y);
    }

    if (tid < 48) cbs[tid] = c_cb[tid];
    __syncthreads();

    for (int layer = 0; layer <= N_LAYERS; ++layer) {
        const bool first = (layer == 0);
        const bool last  = (layer == N_LAYERS);

        // gate values this thread needs, in registers (t = 64q + tp)
        float gvv[8];
        if (!first) {
#pragma unroll
            for (int q = 0; q < 8; ++q) gvv[q] = __ldcg(&g_gate[(q << 6) + tp]);
        }

        float acc[8];                              // per-thread |R|^2 partials
#pragma unroll
        for (int q = 0; q < 8; ++q) acc[q] = 0.f;

        int par = 0;
        for (int tile = blockIdx.x; tile < NTILES; tile += GRID) {
            const int b0 = tile * TILE_R;
            cplx* Gb = Gs + par * GSIZE;

            // ---- stage G: hh = R*g (regs); Gb[r][dd][tp] = wtw[dd] * fft8_q(hh) ----
            cplx hh[8];
            if (!first) {
                cplx X[8];
#pragma unroll
                for (int q = 0; q < 8; ++q) {
                    cplx Rv = __ldcg(&g_R[(b0 + r) * T_S + (q << 6) + tp]);
                    hh[q] = f2mul(Rv, PK(gvv[q], gvv[q]));
                }
                fft8f(hh, X);
#pragma unroll
                for (int dd = 0; dd < 8; ++dd) {
                    float2 y = cmul(UPK(X[dd]), UPK(wtw[dd]));
                    Gb[(r * 8 + dd) * GPAD + tp] = PK(y.x, y.y);
                }
            } else {
#pragma unroll
                for (int q = 0; q < 8; ++q) hh[q] = PK(0.f, 0.f);
            }
            NBAR(bar_id);

            // ---- fused stage A+S (role (r,d,b)) ----
            {
                cplx p[6];
                if (!first) {
                    cplx Gv[8], A[8];
#pragma unroll
                    for (int a = 0; a < 8; ++a) Gv[a] = Gb[(r * 8 + d) * GPAD + (a << 3) + b];
                    fft8f(Gv, A);
#pragma unroll
                    for (int c = 0; c < 6; ++c) {
                        float2 t = cmul(UPK(A[c]), cbs[c * 8 + b]);
                        p[c] = PK(t.x, t.y);
                    }
#pragma unroll
                    for (int m = 1; m < 8; m <<= 1) {
#pragma unroll
                        for (int c = 0; c < 6; ++c) {
                            float2 t = UPK(p[c]);
                            float lx = __shfl_xor_sync(0xFFFFFFFFu, t.x, m);
                            float ly = __shfl_xor_sync(0xFFFFFFFFu, t.y, m);
                            p[c] = f2add(p[c], PK(lx, ly));
                        }
                    }
                } else {
#pragma unroll
                    for (int c = 0; c < 6; ++c) p[c] = PK(0.f, 0.f);
                }

                if (last) {
                    if (b == 0) {
                        const float s_out = g_scale[1];
#pragma unroll
                        for (int c = 0; c < 6; ++c) {
                            float2 pv = UPK(p[c]);
                            ((float2*)out)[(b0 + r) * F_S + (c << 3) + d] =
                                make_float2(pv.x * s_out, pv.y * s_out);
                        }
                    }
                    par ^= 1;      // double buffer: next G writes other half
                    continue;
                }

                cplx v[8], S[8];
#pragma unroll
                for (int c = 0; c < 6; ++c) {
                    float2 uv = ((const float2*)u)[(b0 + r) * F_S + (c << 3) + d];
                    float2 pv = UPK(p[c]);
                    float2 z = make_float2(uv.x * s_in - pv.x, uv.y * s_in - pv.y);
                    float2 w = cmulj(z, cbs[c * 8 + b]);
                    v[c] = PK(w.x, w.y);
                }
                v[6] = PK(0.f, 0.f);
                v[7] = PK(0.f, 0.f);
                fft8i(v, S);
#pragma unroll
                for (int a = 0; a < 8; ++a)
                    Gb[(r * 8 + d) * GPAD + (a << 3) + b] = S[a];   // same slots this thread read
            }
            NBAR(bar_id);

            // ---- stage Z/R: Z = ifft8_d( Gb[d][tp] * conj(wtw[d]) ); R = hh + Z ----
            {
                cplx v[8], Z[8];
#pragma unroll
                for (int dd = 0; dd < 8; ++dd) {
                    float2 w = cmulj(UPK(Gb[(r * 8 + dd) * GPAD + tp]), UPK(wtw[dd]));
                    v[dd] = PK(w.x, w.y);
                }
                fft8i(v, Z);
#pragma unroll
                for (int q = 0; q < 8; ++q) {
                    cplx Rp = f2add(Z[q], hh[q]);
                    g_R[(b0 + r) * T_S + (q << 6) + tp] = Rp;
                    float2 Rv = UPK(Rp);
                    acc[q] = fmaf(Rv.x, Rv.x, fmaf(Rv.y, Rv.y, acc[q]));
                }
            }
            par ^= 1;              // double buffer: next G writes other half, no barrier
        }
        if (last) break;

        // ---- per-layer |R|^2 reduction: regs -> smem (r groups) -> per-CTA partial ----
#pragma unroll
        for (int q = 0; q < 8; ++q) ps2[r * T_S + (q << 6) + tp] = acc[q];
        __syncthreads();
        for (int t = tid; t < T_S; t += THREADS)
            g_partial[t * GRID + blockIdx.x] =
                ps2[t] + ps2[T_S + t] + ps2[2 * T_S + t] + ps2[3 * T_S + t];
        grid_bar();

        // -------- gate stage --------
        for (int t = blockIdx.x; t < T_S; t += GRID) {
            float s = __ldcg(&g_partial[t * GRID + tid]);
            if (tid + 256 < GRID) s += __ldcg(&g_partial[t * GRID + tid + 256]);
            red[tid] = s;
            __syncthreads();
            for (int k = 128; k > 0; k >>= 1) {
                if (tid < k) red[tid] += red[tid + k];
                __syncthreads();
            }
            if (tid == 0) {
                float rmean = sqrtf(red[0] * (1.0f / (float)B_TOTAL));
                float x = S1[0] * (rmean - S2[0]);
                g_gate[t] = 1.0f / (1.0f + expf(-x));
            }
            __syncthreads();
        }
        grid_bar();
    }
}

// ---------------- launch ----------------
extern "C" void kernel_launch(void* const* d_in, const int* in_sizes, int n_in,
                              void* d_out, int out_size) {
    const float* u  = (const float*)d_in[0];
    const float* S1 = (const float*)d_in[1];
    const float* S2 = (const float*)d_in[2];
    float* out = (float*)d_out;

    const int smem = (2 * GSIZE) * (int)sizeof(cplx)
                   + 48 * (int)sizeof(float2)
                   + (4 * T_S + THREADS) * (int)sizeof(float);
    cudaFuncSetAttribute(k_net, cudaFuncAttributeMaxDynamicSharedMemorySize, smem);

    const int n = B_TOTAL * F_S * 2;
    k_max1<<<256, 256>>>(u, n);
    k_max2<<<1, 256>>>();
    k_tw<<<2, 256>>>();
    k_net<<<GRID, THREADS, smem>>>(u, S1, S2, out);

    (void)in_sizes; (void)n_in; (void)out_size;
}